// round 3
// baseline (speedup 1.0000x reference)
#include <cuda_runtime.h>
#include <cuda_bf16.h>
#include <math.h>

// Problem shape (fixed by the reference)
#define BB 4
#define SS 4096
#define DD 512
#define FF 2048
#define MTOT (BB * SS)   // 16384

// ---------------------------------------------------------------------------
// Scratch (static device globals; no runtime allocation allowed)
// ---------------------------------------------------------------------------
__device__ float g_Q[(size_t)MTOT * DD];
__device__ float g_K[(size_t)MTOT * DD];
__device__ float g_V[(size_t)MTOT * DD];
__device__ float g_P[(size_t)BB * SS * SS];   // attention scores / probs (268 MB)
__device__ float g_att[(size_t)MTOT * DD];
__device__ float g_x1[(size_t)MTOT * DD];
__device__ float g_h[(size_t)MTOT * FF];
__device__ float g_f[(size_t)MTOT * DD];

// ---------------------------------------------------------------------------
// Tiled SGEMM: C[M,N] = alpha * A[M,K] @ B + bias, optional ReLU.
// TRANSB=false: B is [K,N] row-major.  TRANSB=true: B is [N,K] row-major (C=A@B^T).
// BM=BN=128, BK=8, 256 threads, 8x8 microtile per thread.
// All dims assumed multiples of the tile (true for this problem).
// blockIdx.z batches with strides sA/sB/sC.
// ---------------------------------------------------------------------------
template <bool TRANSB, bool RELU>
__global__ __launch_bounds__(256, 2)
void gemm128(const float* __restrict__ A, const float* __restrict__ Bm,
             const float* __restrict__ bias, float* __restrict__ C,
             int M, int N, int K, float alpha,
             size_t sA, size_t sB, size_t sC)
{
    __shared__ float As[8][132];   // [BK][BM] transposed, padded to 132 (16B-aligned rows)
    __shared__ float Bs[8][132];   // [BK][BN]

    A  += (size_t)blockIdx.z * sA;
    Bm += (size_t)blockIdx.z * sB;
    C  += (size_t)blockIdx.z * sC;

    const int m0 = blockIdx.y * 128;
    const int n0 = blockIdx.x * 128;
    const int tx = threadIdx.x;       // n-direction, 0..15
    const int ty = threadIdx.y;       // m-direction, 0..15
    const int tid = ty * 16 + tx;

    float acc[8][8];
#pragma unroll
    for (int i = 0; i < 8; i++)
#pragma unroll
        for (int j = 0; j < 8; j++) acc[i][j] = 0.f;

    const int rowA = tid >> 1;            // 0..127
    const int cA4  = (tid & 1) * 4;       // 0 or 4

    for (int k0 = 0; k0 < K; k0 += 8) {
        // --- load A tile [128 x 8], store transposed into As[k][m] ---
        {
            float4 av = *(const float4*)(A + (size_t)(m0 + rowA) * K + k0 + cA4);
            As[cA4 + 0][rowA] = av.x;
            As[cA4 + 1][rowA] = av.y;
            As[cA4 + 2][rowA] = av.z;
            As[cA4 + 3][rowA] = av.w;
        }
        // --- load B tile [8 x 128] ---
        if (!TRANSB) {
            int kkB = tid >> 5;            // 0..7
            int n4  = (tid & 31) * 4;      // 0..124
            float4 bv = *(const float4*)(Bm + (size_t)(k0 + kkB) * N + n0 + n4);
            *(float4*)&Bs[kkB][n4] = bv;
        } else {
            int nB = tid >> 1;             // 0..127
            int k4 = (tid & 1) * 4;        // 0 or 4
            float4 bv = *(const float4*)(Bm + (size_t)(n0 + nB) * K + k0 + k4);
            Bs[k4 + 0][nB] = bv.x;
            Bs[k4 + 1][nB] = bv.y;
            Bs[k4 + 2][nB] = bv.z;
            Bs[k4 + 3][nB] = bv.w;
        }
        __syncthreads();

#pragma unroll
        for (int kk = 0; kk < 8; kk++) {
            float a[8], b[8];
            float4 t;
            t = *(const float4*)&As[kk][ty * 8];     a[0]=t.x; a[1]=t.y; a[2]=t.z; a[3]=t.w;
            t = *(const float4*)&As[kk][ty * 8 + 4]; a[4]=t.x; a[5]=t.y; a[6]=t.z; a[7]=t.w;
            t = *(const float4*)&Bs[kk][tx * 8];     b[0]=t.x; b[1]=t.y; b[2]=t.z; b[3]=t.w;
            t = *(const float4*)&Bs[kk][tx * 8 + 4]; b[4]=t.x; b[5]=t.y; b[6]=t.z; b[7]=t.w;
#pragma unroll
            for (int i = 0; i < 8; i++)
#pragma unroll
                for (int j = 0; j < 8; j++)
                    acc[i][j] = fmaf(a[i], b[j], acc[i][j]);
        }
        __syncthreads();
    }

    // --- epilogue ---
    float bv[8];
#pragma unroll
    for (int j = 0; j < 8; j++)
        bv[j] = bias ? bias[n0 + tx * 8 + j] : 0.f;

#pragma unroll
    for (int i = 0; i < 8; i++) {
        float* crow = C + (size_t)(m0 + ty * 8 + i) * N + n0 + tx * 8;
        float4 o0, o1;
        float v[8];
#pragma unroll
        for (int j = 0; j < 8; j++) {
            float t = alpha * acc[i][j] + bv[j];
            if (RELU) t = fmaxf(t, 0.f);
            v[j] = t;
        }
        o0.x=v[0]; o0.y=v[1]; o0.z=v[2]; o0.w=v[3];
        o1.x=v[4]; o1.y=v[5]; o1.z=v[6]; o1.w=v[7];
        *(float4*)(crow)     = o0;
        *(float4*)(crow + 4) = o1;
    }
}

// ---------------------------------------------------------------------------
// Row softmax in place. One block (256 threads) per row of length n.
// ---------------------------------------------------------------------------
__global__ void softmax_rows(float* __restrict__ P, int n)
{
    const size_t row = blockIdx.x;
    float* p = P + row * (size_t)n;
    const int tid = threadIdx.x;
    __shared__ float red[8];

    // max
    float m = -INFINITY;
    for (int i = tid; i < n; i += 256) m = fmaxf(m, p[i]);
#pragma unroll
    for (int o = 16; o > 0; o >>= 1) m = fmaxf(m, __shfl_xor_sync(0xffffffffu, m, o));
    if ((tid & 31) == 0) red[tid >> 5] = m;
    __syncthreads();
    m = red[0];
#pragma unroll
    for (int w = 1; w < 8; w++) m = fmaxf(m, red[w]);
    __syncthreads();

    // exp + sum
    float s = 0.f;
    for (int i = tid; i < n; i += 256) {
        float e = expf(p[i] - m);
        p[i] = e;
        s += e;
    }
#pragma unroll
    for (int o = 16; o > 0; o >>= 1) s += __shfl_xor_sync(0xffffffffu, s, o);
    if ((tid & 31) == 0) red[tid >> 5] = s;
    __syncthreads();
    s = red[0];
#pragma unroll
    for (int w = 1; w < 8; w++) s += red[w];
    const float inv = 1.f / s;

    for (int i = tid; i < n; i += 256) p[i] *= inv;
}

// ---------------------------------------------------------------------------
// y = LayerNorm(x + r) * g + b, row length 512. One block (128 threads) per row.
// ---------------------------------------------------------------------------
__global__ void add_ln(const float* __restrict__ x, const float* __restrict__ r,
                       const float* __restrict__ g, const float* __restrict__ b,
                       float* __restrict__ y)
{
    const size_t row = blockIdx.x;
    const int tid = threadIdx.x;
    const int lane = tid & 31, wid = tid >> 5;
    __shared__ float red[4];

    float4 xv = *(const float4*)(x + row * DD + tid * 4);
    float4 rv = *(const float4*)(r + row * DD + tid * 4);
    float v0 = xv.x + rv.x, v1 = xv.y + rv.y, v2 = xv.z + rv.z, v3 = xv.w + rv.w;

    // mean
    float s = v0 + v1 + v2 + v3;
#pragma unroll
    for (int o = 16; o > 0; o >>= 1) s += __shfl_xor_sync(0xffffffffu, s, o);
    if (lane == 0) red[wid] = s;
    __syncthreads();
    float mu = (red[0] + red[1] + red[2] + red[3]) * (1.f / DD);
    __syncthreads();

    float d0 = v0 - mu, d1 = v1 - mu, d2 = v2 - mu, d3 = v3 - mu;
    float sq = d0*d0 + d1*d1 + d2*d2 + d3*d3;
#pragma unroll
    for (int o = 16; o > 0; o >>= 1) sq += __shfl_xor_sync(0xffffffffu, sq, o);
    if (lane == 0) red[wid] = sq;
    __syncthreads();
    float var = (red[0] + red[1] + red[2] + red[3]) * (1.f / DD);
    float rstd = rsqrtf(var + 1e-5f);

    float4 gv = *(const float4*)(g + tid * 4);
    float4 bv = *(const float4*)(b + tid * 4);
    float4 o;
    o.x = d0 * rstd * gv.x + bv.x;
    o.y = d1 * rstd * gv.y + bv.y;
    o.z = d2 * rstd * gv.z + bv.z;
    o.w = d3 * rstd * gv.w + bv.w;
    *(float4*)(y + row * DD + tid * 4) = o;
}

// ---------------------------------------------------------------------------
// Launch
// ---------------------------------------------------------------------------
extern "C" void kernel_launch(void* const* d_in, const int* in_sizes, int n_in,
                              void* d_out, int out_size)
{
    const float* x   = (const float*)d_in[0];
    const float* Wq  = (const float*)d_in[1];
    const float* bq  = (const float*)d_in[2];
    const float* Wk  = (const float*)d_in[3];
    const float* bk  = (const float*)d_in[4];
    const float* Wv  = (const float*)d_in[5];
    const float* bv  = (const float*)d_in[6];
    const float* g1  = (const float*)d_in[7];
    const float* b1  = (const float*)d_in[8];
    const float* g2  = (const float*)d_in[9];
    const float* b2  = (const float*)d_in[10];
    const float* W1  = (const float*)d_in[11];
    const float* bf1 = (const float*)d_in[12];
    const float* W2  = (const float*)d_in[13];
    const float* bf2 = (const float*)d_in[14];
    float* out = (float*)d_out;

    float *Q, *K, *V, *P, *att, *x1, *h, *f;
    cudaGetSymbolAddress((void**)&Q,   g_Q);
    cudaGetSymbolAddress((void**)&K,   g_K);
    cudaGetSymbolAddress((void**)&V,   g_V);
    cudaGetSymbolAddress((void**)&P,   g_P);
    cudaGetSymbolAddress((void**)&att, g_att);
    cudaGetSymbolAddress((void**)&x1,  g_x1);
    cudaGetSymbolAddress((void**)&h,   g_h);
    cudaGetSymbolAddress((void**)&f,   g_f);

    const dim3 blk(16, 16);
    const float scale = 1.f / sqrtf((float)DD);

    // QKV projections: [16384,512] = x @ W + b
    gemm128<false, false><<<dim3(DD/128, MTOT/128, 1), blk>>>(x, Wq, bq, Q, MTOT, DD, DD, 1.f, 0, 0, 0);
    gemm128<false, false><<<dim3(DD/128, MTOT/128, 1), blk>>>(x, Wk, bk, K, MTOT, DD, DD, 1.f, 0, 0, 0);
    gemm128<false, false><<<dim3(DD/128, MTOT/128, 1), blk>>>(x, Wv, bv, V, MTOT, DD, DD, 1.f, 0, 0, 0);

    // scores: P[b] = scale * Q[b] @ K[b]^T   [4096 x 4096] per batch
    gemm128<true, false><<<dim3(SS/128, SS/128, BB), blk>>>(
        Q, K, nullptr, P, SS, SS, DD, scale,
        (size_t)SS * DD, (size_t)SS * DD, (size_t)SS * SS);

    // softmax rows
    softmax_rows<<<BB * SS, 256>>>(P, SS);

    // att[b] = P[b] @ V[b]   [4096 x 512]
    gemm128<false, false><<<dim3(DD/128, SS/128, BB), blk>>>(
        P, V, nullptr, att, SS, DD, SS, 1.f,
        (size_t)SS * SS, (size_t)SS * DD, (size_t)SS * DD);

    // x1 = LN(x + att)
    add_ln<<<MTOT, 128>>>(x, att, g1, b1, x1);

    // h = relu(x1 @ W1 + bf1)   [16384 x 2048]
    gemm128<false, true><<<dim3(FF/128, MTOT/128, 1), blk>>>(x1, W1, bf1, h, MTOT, FF, DD, 1.f, 0, 0, 0);

    // f = h @ W2 + bf2   [16384 x 512]
    gemm128<false, false><<<dim3(DD/128, MTOT/128, 1), blk>>>(h, W2, bf2, f, MTOT, DD, FF, 1.f, 0, 0, 0);

    // out = LN(x1 + f)
    add_ln<<<MTOT, 128>>>(x1, f, g2, b2, out);
}

// round 7
// speedup vs baseline: 3.5478x; 3.5478x over previous
#include <cuda_runtime.h>
#include <cuda_bf16.h>
#include <math.h>
#include <stdint.h>

// Problem shape (fixed)
#define BB 4
#define SS 4096
#define DD 512
#define FF 2048
#define MTOT (BB * SS)   // 16384

// ---------------------------------------------------------------------------
// Scratch (static device globals; no runtime allocation allowed)
// ---------------------------------------------------------------------------
__device__ float g_xr  [(size_t)MTOT * DD];        // tf32-rounded x
__device__ float g_qkv [(size_t)MTOT * 3 * DD];    // fused QKV out [M,1536]
__device__ float g_P   [(size_t)BB * SS * SS];     // scores / probs
__device__ float g_Vt  [(size_t)BB * DD * SS];     // V^T per batch [512,4096]
__device__ float g_att [(size_t)MTOT * DD];
__device__ float g_x1  [(size_t)MTOT * DD];
__device__ float g_h   [(size_t)MTOT * FF];
__device__ float g_f   [(size_t)MTOT * DD];
__device__ float g_WqkvT[(size_t)3 * DD * DD];     // [1536,512]
__device__ float g_W1T [(size_t)FF * DD];          // [2048,512]
__device__ float g_W2T [(size_t)DD * FF];          // [512,2048]
__device__ float g_bqkv[3 * DD];

// ---------------------------------------------------------------------------
// Helpers
// ---------------------------------------------------------------------------
__device__ __forceinline__ float tf32r(float x) {
    uint32_t u;
    asm("cvt.rna.tf32.f32 %0, %1;" : "=r"(u) : "f"(x));
    return __uint_as_float(u);
}

#define CPA16(dst, src) \
    asm volatile("cp.async.cg.shared.global [%0], [%1], 16;" :: "r"(dst), "l"(src))
#define CPA_COMMIT() asm volatile("cp.async.commit_group;" ::: "memory")
#define CPA_WAIT1()  asm volatile("cp.async.wait_group 1;" ::: "memory")

__device__ __forceinline__ uint32_t smem_u32(const void* p) {
    uint32_t a;
    asm("{ .reg .u64 t; cvta.to.shared.u64 t, %1; cvt.u32.u64 %0, t; }"
        : "=r"(a) : "l"(p));
    return a;
}

// mma.sync m16n8k8 tf32: D += A @ B  (A 16x8 row, B 8x8 col)
__device__ __forceinline__ void mma8(float* c, const uint32_t* a, const uint32_t* b) {
    asm volatile(
        "mma.sync.aligned.m16n8k8.row.col.f32.tf32.tf32.f32 "
        "{%0,%1,%2,%3}, {%4,%5,%6,%7}, {%8,%9}, {%0,%1,%2,%3};"
        : "+f"(c[0]), "+f"(c[1]), "+f"(c[2]), "+f"(c[3])
        : "r"(a[0]), "r"(a[1]), "r"(a[2]), "r"(a[3]), "r"(b[0]), "r"(b[1]));
}

// ---------------------------------------------------------------------------
// tf32 mma.sync GEMM: C[M,N] = alpha * A[M,K] @ B[N,K]^T + bias (+ReLU, +round)
// Tile 128x128xBK32, 3-stage cp.async, 128 threads = 4 warps (2m x 2n),
// warp tile 64x64 (4 mfrag x 8 nfrag of m16n8k8).
// SMEM rows padded to 36 floats (conflict-free fragment LDS).
// grid = (N/128, M/128, Z). All dims multiples of tile.
// ---------------------------------------------------------------------------
#define STAGES 3
#define PADF 36
#define A_FL (128 * PADF)          // floats per A stage
#define STAGE_FL (2 * 128 * PADF)  // A + B
#define DYN_SMEM (STAGES * STAGE_FL * 4)  // 110592 B

template <bool RELU, bool ROUND>
__global__ __launch_bounds__(128)
void gemm_mma(const float* __restrict__ A, const float* __restrict__ B,
              const float* __restrict__ bias, float* __restrict__ C,
              int K, long lda, long ldb, long ldc,
              long sA, long sB, long sC, float alpha)
{
    extern __shared__ float smf[];
    const uint32_t smb = smem_u32(smf);

    const int tid  = threadIdx.x;
    const int wid  = tid >> 5;
    const int lane = tid & 31;
    const int g    = lane >> 2;     // groupID 0..7
    const int tig  = lane & 3;      // threadID_in_group
    const int wm   = wid & 1;       // 2 warps in m
    const int wn   = wid >> 1;      // 2 warps in n
    const int bz   = blockIdx.z;
    const int m0   = blockIdx.y * 128;
    const int n0   = blockIdx.x * 128;

    const float* Atile = A + (size_t)bz * sA + (size_t)m0 * lda;
    const float* Btile = B + (size_t)bz * sB + (size_t)n0 * ldb;
    const int NKB = K >> 5;

    auto load_stage = [&](int kb, int s) {
        const float* Ab = Atile + (size_t)kb * 32;
        const float* Bb = Btile + (size_t)kb * 32;
        const uint32_t sa = smb + (uint32_t)(s * STAGE_FL) * 4u;
        const uint32_t sb = sa + (uint32_t)A_FL * 4u;
#pragma unroll
        for (int i = 0; i < 8; i++) {
            int u = i * 128 + tid;
            int r = u >> 3, kc = u & 7;
            CPA16(sa + (uint32_t)(r * PADF + kc * 4) * 4u, Ab + (size_t)r * lda + kc * 4);
        }
#pragma unroll
        for (int i = 0; i < 8; i++) {
            int u = i * 128 + tid;
            int r = u >> 3, kc = u & 7;
            CPA16(sb + (uint32_t)(r * PADF + kc * 4) * 4u, Bb + (size_t)r * ldb + kc * 4);
        }
        CPA_COMMIT();
    };

    float c[4][8][4];
#pragma unroll
    for (int mf = 0; mf < 4; mf++)
#pragma unroll
        for (int nf = 0; nf < 8; nf++)
#pragma unroll
            for (int k = 0; k < 4; k++) c[mf][nf][k] = 0.f;

    // prologue: fill STAGES-1 stages
#pragma unroll
    for (int s = 0; s < STAGES - 1; s++)
        if (s < NKB) load_stage(s, s);

    const int aBase = (wm * 64 + g) * PADF + tig;   // float index, mf0/ks0
    const int bBase = (wn * 64 + g) * PADF + tig;

    for (int kb = 0; kb < NKB; kb++) {
        CPA_WAIT1();
        __syncthreads();

        const int ldkb = kb + STAGES - 1;
        if (ldkb < NKB) load_stage(ldkb, ldkb % STAGES);
        else            CPA_COMMIT();

        const float* sA = smf + (kb % STAGES) * STAGE_FL;
        const float* sB = sA + A_FL;

#pragma unroll
        for (int ks = 0; ks < 4; ks++) {
            uint32_t af[4][4], bf[8][2];
#pragma unroll
            for (int mf = 0; mf < 4; mf++) {
                const float* p = sA + aBase + mf * (16 * PADF) + ks * 8;
                af[mf][0] = __float_as_uint(p[0]);            // (g,    k=tig)
                af[mf][1] = __float_as_uint(p[8 * PADF]);     // (g+8,  k=tig)
                af[mf][2] = __float_as_uint(p[4]);            // (g,    k=tig+4)
                af[mf][3] = __float_as_uint(p[8 * PADF + 4]); // (g+8,  k=tig+4)
            }
#pragma unroll
            for (int nf = 0; nf < 8; nf++) {
                const float* p = sB + bBase + nf * (8 * PADF) + ks * 8;
                bf[nf][0] = __float_as_uint(p[0]);            // (k=tig,   n=g)
                bf[nf][1] = __float_as_uint(p[4]);            // (k=tig+4, n=g)
            }
#pragma unroll
            for (int mf = 0; mf < 4; mf++)
#pragma unroll
                for (int nf = 0; nf < 8; nf++)
                    mma8(c[mf][nf], af[mf], bf[nf]);
        }
    }

    // epilogue: c layout per thread: rows g / g+8, cols 2tig / 2tig+1
    float* Cb = C + (size_t)bz * sC;
#pragma unroll
    for (int mf = 0; mf < 4; mf++) {
        const int row0 = m0 + wm * 64 + mf * 16 + g;
#pragma unroll
        for (int nf = 0; nf < 8; nf++) {
            const int col = n0 + wn * 64 + nf * 8 + 2 * tig;
            float b0 = 0.f, b1 = 0.f;
            if (bias) { b0 = __ldg(&bias[col]); b1 = __ldg(&bias[col + 1]); }
            float v0 = alpha * c[mf][nf][0] + b0;
            float v1 = alpha * c[mf][nf][1] + b1;
            float v2 = alpha * c[mf][nf][2] + b0;
            float v3 = alpha * c[mf][nf][3] + b1;
            if (RELU) {
                v0 = fmaxf(v0, 0.f); v1 = fmaxf(v1, 0.f);
                v2 = fmaxf(v2, 0.f); v3 = fmaxf(v3, 0.f);
            }
            if (ROUND) {
                v0 = tf32r(v0); v1 = tf32r(v1); v2 = tf32r(v2); v3 = tf32r(v3);
            }
            float2 lo; lo.x = v0; lo.y = v1;
            float2 hi; hi.x = v2; hi.y = v3;
            *(float2*)(Cb + (size_t)row0 * ldc + col)       = lo;
            *(float2*)(Cb + (size_t)(row0 + 8) * ldc + col) = hi;
        }
    }
}

// ---------------------------------------------------------------------------
// elementwise tf32 round copy
// ---------------------------------------------------------------------------
__global__ void round_copy(const float* __restrict__ in, float* __restrict__ out, size_t n4)
{
    size_t i = (size_t)blockIdx.x * blockDim.x + threadIdx.x;
    size_t stride = (size_t)gridDim.x * blockDim.x;
    for (; i < n4; i += stride) {
        float4 v = ((const float4*)in)[i];
        v.x = tf32r(v.x); v.y = tf32r(v.y); v.z = tf32r(v.z); v.w = tf32r(v.w);
        ((float4*)out)[i] = v;
    }
}

// concat bias vectors (fp32, no rounding — bias is added post-MMA)
__global__ void concat_bias(const float* __restrict__ a, const float* __restrict__ b,
                            const float* __restrict__ c, float* __restrict__ o)
{
    int i = blockIdx.x * blockDim.x + threadIdx.x;
    if (i < DD)           o[i] = a[i];
    else if (i < 2 * DD)  o[i] = b[i - DD];
    else if (i < 3 * DD)  o[i] = c[i - 2 * DD];
}

// ---------------------------------------------------------------------------
// Tiled transpose with tf32 rounding: out[c, r] = rnd(in[r, c]).
// grid = (C/32, R/32, Z). block = (32, 8).
// ---------------------------------------------------------------------------
__global__ void transpose_rnd(const float* __restrict__ in, float* __restrict__ out,
                              long ldi, long ldo, long sIn, long sOut)
{
    __shared__ float t[32][33];
    in  += (size_t)blockIdx.z * sIn;
    out += (size_t)blockIdx.z * sOut;
    const int r0 = blockIdx.y * 32, c0 = blockIdx.x * 32;
    const int x = threadIdx.x, y = threadIdx.y;
#pragma unroll
    for (int i = 0; i < 32; i += 8)
        t[y + i][x] = in[(size_t)(r0 + y + i) * ldi + c0 + x];
    __syncthreads();
#pragma unroll
    for (int i = 0; i < 32; i += 8)
        out[(size_t)(c0 + y + i) * ldo + r0 + x] = tf32r(t[x][y + i]);
}

// ---------------------------------------------------------------------------
// Row softmax in place, tf32-rounded output. One block (256 threads) per row.
// ---------------------------------------------------------------------------
__global__ void softmax_rows(float* __restrict__ P, int n)
{
    const size_t row = blockIdx.x;
    float* p = P + row * (size_t)n;
    const int tid = threadIdx.x;
    __shared__ float red[8];

    float m = -INFINITY;
    for (int i = tid; i < n; i += 256) m = fmaxf(m, p[i]);
#pragma unroll
    for (int o = 16; o > 0; o >>= 1) m = fmaxf(m, __shfl_xor_sync(0xffffffffu, m, o));
    if ((tid & 31) == 0) red[tid >> 5] = m;
    __syncthreads();
    m = red[0];
#pragma unroll
    for (int w = 1; w < 8; w++) m = fmaxf(m, red[w]);
    __syncthreads();

    float s = 0.f;
    for (int i = tid; i < n; i += 256) {
        float e = expf(p[i] - m);
        p[i] = e;
        s += e;
    }
#pragma unroll
    for (int o = 16; o > 0; o >>= 1) s += __shfl_xor_sync(0xffffffffu, s, o);
    if ((tid & 31) == 0) red[tid >> 5] = s;
    __syncthreads();
    s = red[0];
#pragma unroll
    for (int w = 1; w < 8; w++) s += red[w];
    const float inv = 1.f / s;

    for (int i = tid; i < n; i += 256) p[i] = tf32r(p[i] * inv);
}

// ---------------------------------------------------------------------------
// y = LayerNorm(x + r) * g + b, row length 512. One block (128 threads) per row.
// ---------------------------------------------------------------------------
template <bool ROUND>
__global__ void add_ln(const float* __restrict__ x, const float* __restrict__ r,
                       const float* __restrict__ g, const float* __restrict__ b,
                       float* __restrict__ y)
{
    const size_t row = blockIdx.x;
    const int tid = threadIdx.x;
    const int lane = tid & 31, wid = tid >> 5;
    __shared__ float red[4];

    float4 xv = *(const float4*)(x + row * DD + tid * 4);
    float4 rv = *(const float4*)(r + row * DD + tid * 4);
    float v0 = xv.x + rv.x, v1 = xv.y + rv.y, v2 = xv.z + rv.z, v3 = xv.w + rv.w;

    float s = v0 + v1 + v2 + v3;
#pragma unroll
    for (int o = 16; o > 0; o >>= 1) s += __shfl_xor_sync(0xffffffffu, s, o);
    if (lane == 0) red[wid] = s;
    __syncthreads();
    float mu = (red[0] + red[1] + red[2] + red[3]) * (1.f / DD);
    __syncthreads();

    float d0 = v0 - mu, d1 = v1 - mu, d2 = v2 - mu, d3 = v3 - mu;
    float sq = d0*d0 + d1*d1 + d2*d2 + d3*d3;
#pragma unroll
    for (int o = 16; o > 0; o >>= 1) sq += __shfl_xor_sync(0xffffffffu, sq, o);
    if (lane == 0) red[wid] = sq;
    __syncthreads();
    float var = (red[0] + red[1] + red[2] + red[3]) * (1.f / DD);
    float rstd = rsqrtf(var + 1e-5f);

    float4 gv = *(const float4*)(g + tid * 4);
    float4 bv = *(const float4*)(b + tid * 4);
    float4 o;
    o.x = d0 * rstd * gv.x + bv.x;
    o.y = d1 * rstd * gv.y + bv.y;
    o.z = d2 * rstd * gv.z + bv.z;
    o.w = d3 * rstd * gv.w + bv.w;
    if (ROUND) { o.x = tf32r(o.x); o.y = tf32r(o.y); o.z = tf32r(o.z); o.w = tf32r(o.w); }
    *(float4*)(y + row * DD + tid * 4) = o;
}

// ---------------------------------------------------------------------------
// Launch
// ---------------------------------------------------------------------------
extern "C" void kernel_launch(void* const* d_in, const int* in_sizes, int n_in,
                              void* d_out, int out_size)
{
    const float* x   = (const float*)d_in[0];
    const float* Wq  = (const float*)d_in[1];
    const float* bq  = (const float*)d_in[2];
    const float* Wk  = (const float*)d_in[3];
    const float* bk  = (const float*)d_in[4];
    const float* Wv  = (const float*)d_in[5];
    const float* bv  = (const float*)d_in[6];
    const float* g1  = (const float*)d_in[7];
    const float* b1  = (const float*)d_in[8];
    const float* g2  = (const float*)d_in[9];
    const float* b2  = (const float*)d_in[10];
    const float* W1  = (const float*)d_in[11];
    const float* bf1 = (const float*)d_in[12];
    const float* W2  = (const float*)d_in[13];
    const float* bf2 = (const float*)d_in[14];
    float* out = (float*)d_out;

    float *xr, *qkv, *P, *Vt, *att, *x1, *h, *f, *WqkvT, *W1T, *W2T, *bqkv;
    cudaGetSymbolAddress((void**)&xr,    g_xr);
    cudaGetSymbolAddress((void**)&qkv,   g_qkv);
    cudaGetSymbolAddress((void**)&P,     g_P);
    cudaGetSymbolAddress((void**)&Vt,    g_Vt);
    cudaGetSymbolAddress((void**)&att,   g_att);
    cudaGetSymbolAddress((void**)&x1,    g_x1);
    cudaGetSymbolAddress((void**)&h,     g_h);
    cudaGetSymbolAddress((void**)&f,     g_f);
    cudaGetSymbolAddress((void**)&WqkvT, g_WqkvT);
    cudaGetSymbolAddress((void**)&W1T,   g_W1T);
    cudaGetSymbolAddress((void**)&W2T,   g_W2T);
    cudaGetSymbolAddress((void**)&bqkv,  g_bqkv);

    cudaFuncSetAttribute(gemm_mma<false, false>, cudaFuncAttributeMaxDynamicSharedMemorySize, DYN_SMEM);
    cudaFuncSetAttribute(gemm_mma<false, true>,  cudaFuncAttributeMaxDynamicSharedMemorySize, DYN_SMEM);
    cudaFuncSetAttribute(gemm_mma<true,  true>,  cudaFuncAttributeMaxDynamicSharedMemorySize, DYN_SMEM);

    const dim3 tblk(32, 8);
    const float scale = 1.f / sqrtf((float)DD);

    // --- operand prep: tf32-rounded copies / transposes ---
    round_copy<<<2048, 256>>>(x, xr, (size_t)MTOT * DD / 4);
    transpose_rnd<<<dim3(16, 16, 1), tblk>>>(Wq, WqkvT,             DD, DD, 0, 0);
    transpose_rnd<<<dim3(16, 16, 1), tblk>>>(Wk, WqkvT + DD * DD,   DD, DD, 0, 0);
    transpose_rnd<<<dim3(16, 16, 1), tblk>>>(Wv, WqkvT + 2*DD*DD,   DD, DD, 0, 0);
    transpose_rnd<<<dim3(64, 16, 1), tblk>>>(W1, W1T, FF, DD, 0, 0);
    transpose_rnd<<<dim3(16, 64, 1), tblk>>>(W2, W2T, DD, FF, 0, 0);
    concat_bias<<<6, 256>>>(bq, bk, bv, bqkv);

    // --- fused QKV: [16384,1536] = xr @ WqkvT^T + bqkv (tf32-rounded out) ---
    gemm_mma<false, true><<<dim3(12, 128, 1), 128, DYN_SMEM>>>(
        xr, WqkvT, bqkv, qkv, DD, DD, DD, 3*DD, 0, 0, 0, 1.f);

    // --- scores: P[b] = scale * Q[b] @ K[b]^T ---
    gemm_mma<false, false><<<dim3(32, 32, BB), 128, DYN_SMEM>>>(
        qkv, qkv + DD, nullptr, P, DD, 3*DD, 3*DD, SS,
        (long)SS*3*DD, (long)SS*3*DD, (long)SS*SS, scale);

    // --- softmax (tf32-rounded probs) ---
    softmax_rows<<<BB * SS, 256>>>(P, SS);

    // --- V^T per batch: [512,4096] ---
    transpose_rnd<<<dim3(16, 128, BB), tblk>>>(
        qkv + 2*DD, Vt, 3*DD, SS, (long)SS*3*DD, (long)DD*SS);

    // --- att[b] = P[b] @ V[b] ---
    gemm_mma<false, false><<<dim3(4, 32, BB), 128, DYN_SMEM>>>(
        P, Vt, nullptr, att, SS, SS, SS, DD,
        (long)SS*SS, (long)DD*SS, (long)SS*DD, 1.f);

    // --- x1 = LN(x + att) (tf32-rounded) ---
    add_ln<true><<<MTOT, 128>>>(x, att, g1, b1, x1);

    // --- h = relu(x1 @ W1 + bf1) (tf32-rounded) ---
    gemm_mma<true, true><<<dim3(16, 128, 1), 128, DYN_SMEM>>>(
        x1, W1T, bf1, h, DD, DD, DD, FF, 0, 0, 0, 1.f);

    // --- f = h @ W2 + bf2 ---
    gemm_mma<false, false><<<dim3(4, 128, 1), 128, DYN_SMEM>>>(
        h, W2T, bf2, f, FF, FF, FF, DD, 0, 0, 0, 1.f);

    // --- out = LN(x1 + f) ---
    add_ln<false><<<MTOT, 128>>>(x1, f, g2, b2, out);
}